// round 2
// baseline (speedup 1.0000x reference)
#include <cuda_runtime.h>
#include <math_constants.h>
#include <cstddef>

// Problem constants
#define kB  2
#define kN  2048
#define kD  1024
#define kH  16
#define kHS 64
#define kM  (kB * kN)        // 4096 rows
#define SCALE 0.03125f       // 1024^-0.5

// Scratch (allocation-free rule: __device__ globals)
__device__ float g_qkv[(size_t)kM * 3 * kD];   // (B*N, 3D)
__device__ float g_ctx[(size_t)kM * kD];       // (B*N, D)

// ---------------------------------------------------------------------------
// Generic tiled SGEMM: C[M,N] = A[M,K] @ B[K,N] (+ bias[N] if bias != null)
// 128x128 block tile, K-tile 8, 256 threads, 8x8 micro-tile (split 4+4).
// Smem stride 132 floats = 528 B = 33*16 -> float4-aligned for any row.
// ---------------------------------------------------------------------------
__global__ __launch_bounds__(256) void sgemm128(
    const float* __restrict__ A, const float* __restrict__ Bm,
    const float* __restrict__ bias, float* __restrict__ C,
    int M, int N, int K)
{
    __shared__ float As[8][132];   // transposed: As[k][m]
    __shared__ float Bs[8][132];   // Bs[k][n]

    const int tid = threadIdx.x;
    const int tx = tid & 15;
    const int ty = tid >> 4;

    const int arow = tid >> 1;
    const int acol = (tid & 1) * 4;
    const int brow = tid >> 5;
    const int bcol = (tid & 31) * 4;

    const float* Ap = A + (size_t)(blockIdx.y * 128 + arow) * K + acol;
    const float* Bp = Bm + (size_t)brow * N + blockIdx.x * 128 + bcol;

    float acc[8][8];
    #pragma unroll
    for (int i = 0; i < 8; i++)
        #pragma unroll
        for (int j = 0; j < 8; j++) acc[i][j] = 0.f;

    for (int k0 = 0; k0 < K; k0 += 8) {
        float4 av = *(const float4*)(Ap + k0);
        As[acol + 0][arow] = av.x;
        As[acol + 1][arow] = av.y;
        As[acol + 2][arow] = av.z;
        As[acol + 3][arow] = av.w;
        *(float4*)&Bs[brow][bcol] = *(const float4*)(Bp + (size_t)k0 * N);
        __syncthreads();

        #pragma unroll
        for (int k = 0; k < 8; k++) {
            float a[8], b[8];
            *(float4*)(a)     = *(const float4*)&As[k][ty * 4];
            *(float4*)(a + 4) = *(const float4*)&As[k][64 + ty * 4];
            *(float4*)(b)     = *(const float4*)&Bs[k][tx * 4];
            *(float4*)(b + 4) = *(const float4*)&Bs[k][64 + tx * 4];
            #pragma unroll
            for (int i = 0; i < 8; i++)
                #pragma unroll
                for (int j = 0; j < 8; j++)
                    acc[i][j] = fmaf(a[i], b[j], acc[i][j]);
        }
        __syncthreads();
    }

    #pragma unroll
    for (int i = 0; i < 8; i++) {
        int row = blockIdx.y * 128 + ((i < 4) ? (ty * 4 + i) : (64 + ty * 4 + i - 4));
        #pragma unroll
        for (int jh = 0; jh < 2; jh++) {
            int col = blockIdx.x * 128 + jh * 64 + tx * 4;
            float4 v;
            v.x = acc[i][jh * 4 + 0];
            v.y = acc[i][jh * 4 + 1];
            v.z = acc[i][jh * 4 + 2];
            v.w = acc[i][jh * 4 + 3];
            if (bias) {
                v.x += bias[col + 0];
                v.y += bias[col + 1];
                v.z += bias[col + 2];
                v.w += bias[col + 3];
            }
            *(float4*)(C + (size_t)row * N + col) = v;
        }
    }
}

// ---------------------------------------------------------------------------
// FP32 flash attention over packed qkv buffer.
// Grid: (N/64 q-tiles, B*H). 256 threads = 16x16; each thread: 4 q-rows x 4 cols.
// All smem tiles use stride 65 (odd -> conflict-free transposed stores);
// inner-product reads are SCALAR (stride 65*4B is not float4-aligned).
// ---------------------------------------------------------------------------
__device__ __forceinline__ float rmax16(float v) {
    #pragma unroll
    for (int m = 8; m > 0; m >>= 1)
        v = fmaxf(v, __shfl_xor_sync(0xffffffffu, v, m));
    return v;
}
__device__ __forceinline__ float rsum16(float v) {
    #pragma unroll
    for (int m = 8; m > 0; m >>= 1)
        v += __shfl_xor_sync(0xffffffffu, v, m);
    return v;
}

__global__ __launch_bounds__(256) void flash_attn(
    const float* __restrict__ qkv, const float* __restrict__ mask,
    float* __restrict__ ctx)
{
    extern __shared__ float sm[];
    float* Qs = sm;                 // transposed: Qs[c*65 + r]
    float* Ks = Qs + 64 * 65;       // transposed: Ks[c*65 + key]
    float* Vs = Ks + 64 * 65;       // natural:    Vs[key*65 + c]
    float* Ps = Vs + 64 * 65;       // transposed: Ps[key*65 + q]
    __shared__ float mks[64];

    const int tid = threadIdx.x;
    const int tx = tid & 15;
    const int ty = tid >> 4;
    const int bh = blockIdx.y;
    const int b  = bh / kH;
    const int h  = bh % kH;
    const int q0 = blockIdx.x * 64;

    const float* qbase = qkv + (size_t)b * kN * 3 * kD + h * kHS;
    const float* kbase = qbase + kD;
    const float* vbase = qbase + 2 * kD;

    // Load Q tile transposed
    for (int t = tid; t < 64 * 64; t += 256) {
        int r = t >> 6, c = t & 63;
        Qs[c * 65 + r] = qbase[(size_t)(q0 + r) * (3 * kD) + c];
    }

    float mq[4];
    #pragma unroll
    for (int i = 0; i < 4; i++) mq[i] = mask[b * kN + q0 + ty * 4 + i];

    float m_i[4], l_i[4], acc[4][4];
    #pragma unroll
    for (int i = 0; i < 4; i++) {
        m_i[i] = -CUDART_INF_F;
        l_i[i] = 0.f;
        #pragma unroll
        for (int j = 0; j < 4; j++) acc[i][j] = 0.f;
    }

    for (int kt = 0; kt < kN / 64; kt++) {
        const int kb = kt * 64;
        __syncthreads();  // previous iteration's smem reads done
        for (int t = tid; t < 64 * 64; t += 256) {
            int r = t >> 6, c = t & 63;
            Ks[c * 65 + r] = kbase[(size_t)(kb + r) * (3 * kD) + c];
            Vs[r * 65 + c] = vbase[(size_t)(kb + r) * (3 * kD) + c];
        }
        if (tid < 64) mks[tid] = mask[b * kN + kb + tid];
        __syncthreads();

        // S = Q @ K^T  (per-thread 4x4), scalar smem reads
        float s[4][4];
        #pragma unroll
        for (int i = 0; i < 4; i++)
            #pragma unroll
            for (int j = 0; j < 4; j++) s[i][j] = 0.f;

        #pragma unroll 4
        for (int k = 0; k < 64; k++) {
            const float* qk = &Qs[k * 65 + ty * 4];
            const float* kk = &Ks[k * 65 + tx * 4];
            float av[4], bv[4];
            #pragma unroll
            for (int i = 0; i < 4; i++) av[i] = qk[i];
            #pragma unroll
            for (int j = 0; j < 4; j++) bv[j] = kk[j];
            #pragma unroll
            for (int i = 0; i < 4; i++)
                #pragma unroll
                for (int j = 0; j < 4; j++)
                    s[i][j] = fmaf(av[i], bv[j], s[i][j]);
        }

        float mk[4];
        #pragma unroll
        for (int j = 0; j < 4; j++) mk[j] = mks[tx * 4 + j];

        // scale, mask, exact-zero -> -inf (faithful to reference)
        #pragma unroll
        for (int i = 0; i < 4; i++)
            #pragma unroll
            for (int j = 0; j < 4; j++) {
                float v = (s[i][j] * SCALE) * (mq[i] * mk[j]);
                if (v == 0.f) v = -CUDART_INF_F;
                s[i][j] = v;
            }

        // online softmax update
        #pragma unroll
        for (int i = 0; i < 4; i++) {
            float tm = fmaxf(fmaxf(s[i][0], s[i][1]), fmaxf(s[i][2], s[i][3]));
            tm = rmax16(tm);
            float nm = fmaxf(m_i[i], tm);
            float corr = (m_i[i] == -CUDART_INF_F) ? 0.f : __expf(m_i[i] - nm);
            float p[4], ps = 0.f;
            #pragma unroll
            for (int j = 0; j < 4; j++) {
                p[j] = (nm == -CUDART_INF_F) ? 0.f : __expf(s[i][j] - nm);
                ps += p[j];
            }
            ps = rsum16(ps);
            l_i[i] = l_i[i] * corr + ps;
            m_i[i] = nm;
            #pragma unroll
            for (int j = 0; j < 4; j++) {
                acc[i][j] *= corr;
                // store P transposed: Ps[key][q]
                Ps[(tx * 4 + j) * 65 + ty * 4 + i] = p[j];
            }
        }
        __syncthreads();

        // O += P @ V, scalar smem reads
        #pragma unroll 4
        for (int k = 0; k < 64; k++) {
            const float* pk = &Ps[k * 65 + ty * 4];
            const float* vk = &Vs[k * 65 + tx * 4];
            float pv[4], vv[4];
            #pragma unroll
            for (int i = 0; i < 4; i++) pv[i] = pk[i];
            #pragma unroll
            for (int j = 0; j < 4; j++) vv[j] = vk[j];
            #pragma unroll
            for (int i = 0; i < 4; i++)
                #pragma unroll
                for (int j = 0; j < 4; j++)
                    acc[i][j] = fmaf(pv[i], vv[j], acc[i][j]);
        }
    }

    // epilogue: ctx[b, q, h*HS + c] = acc / l
    #pragma unroll
    for (int i = 0; i < 4; i++) {
        float inv = 1.f / l_i[i];
        int r = q0 + ty * 4 + i;
        #pragma unroll
        for (int j = 0; j < 4; j++) {
            ctx[(size_t)(b * kN + r) * kD + h * kHS + tx * 4 + j] = acc[i][j] * inv;
        }
    }
}

// ---------------------------------------------------------------------------
extern "C" void kernel_launch(void* const* d_in, const int* in_sizes, int n_in,
                              void* d_out, int out_size)
{
    const float* x         = (const float*)d_in[0];
    const float* attn_mask = (const float*)d_in[1];
    const float* Wqkv      = (const float*)d_in[2];
    const float* Wout      = (const float*)d_in[3];
    const float* bout      = (const float*)d_in[4];
    float* out = (float*)d_out;

    float* qkvbuf = nullptr;
    float* ctxbuf = nullptr;
    cudaGetSymbolAddress((void**)&qkvbuf, g_qkv);
    cudaGetSymbolAddress((void**)&ctxbuf, g_ctx);

    const int smem_flash = 4 * 64 * 65 * (int)sizeof(float);  // 66560 B
    cudaFuncSetAttribute(flash_attn, cudaFuncAttributeMaxDynamicSharedMemorySize,
                         smem_flash);

    dim3 blk(256);
    // 1) qkv = x @ Wqkv : (4096,3072,K=1024)
    sgemm128<<<dim3(3 * kD / 128, kM / 128), blk>>>(x, Wqkv, nullptr, qkvbuf,
                                                    kM, 3 * kD, kD);
    // 2) attention
    flash_attn<<<dim3(kN / 64, kB * kH), blk, smem_flash>>>(qkvbuf, attn_mask,
                                                            ctxbuf);
    // 3) out = ctx @ Wout + bout : (4096,1024,K=1024)
    sgemm128<<<dim3(kD / 128, kM / 128), blk>>>(ctxbuf, Wout, bout, out,
                                                kM, kD, kD);
}

// round 4
// speedup vs baseline: 3.0644x; 3.0644x over previous
#include <cuda_runtime.h>
#include <math_constants.h>
#include <cstdint>
#include <cstddef>

// Problem constants
#define kB  2
#define kN  2048
#define kD  1024
#define kH  16
#define kHS 64
#define kM  (kB * kN)        // 4096 rows
#define SCALE 0.03125f       // 1024^-0.5

// Scratch (allocation-free rule: __device__ globals)
__device__ float g_qkv[(size_t)kM * 3 * kD];    // (B*N, 3D) fp32
__device__ float g_ctx[(size_t)kM * kD];        // (B*N, D) tf32-rounded
__device__ float g_xr[(size_t)kM * kD];         // x rounded to tf32
__device__ float g_wqkvT[(size_t)3 * kD * kD];  // Wqkv^T [3D][D] tf32
__device__ float g_woutT[(size_t)kD * kD];      // Wout^T [D][D] tf32

// ============================================================================
// Helpers
// ============================================================================
__device__ __forceinline__ uint32_t smem_u32(const void* p) {
    uint32_t a;
    asm("{ .reg .u64 t; cvta.to.shared.u64 t, %1; cvt.u32.u64 %0, t; }"
        : "=r"(a) : "l"(p));
    return a;
}
__device__ __forceinline__ float tf32_rna(float x) {
    float r;
    asm("cvt.rna.tf32.f32 %0, %1;" : "=f"(r) : "f"(x));
    return r;
}
__device__ __forceinline__ void cp16(uint32_t dst, const void* src) {
    asm volatile("cp.async.cg.shared.global [%0], [%1], 16;" :: "r"(dst), "l"(src));
}
__device__ __forceinline__ void cp_commit() {
    asm volatile("cp.async.commit_group;" ::: "memory");
}
__device__ __forceinline__ void cp_wait2() {
    asm volatile("cp.async.wait_group 2;" ::: "memory");
}

// m16n8k8 tf32 mma, fp32 accumulate in-place
__device__ __forceinline__ void mma8(float* c, const uint32_t* a, const uint32_t* b) {
    asm volatile(
        "mma.sync.aligned.m16n8k8.row.col.f32.tf32.tf32.f32 "
        "{%0,%1,%2,%3}, {%4,%5,%6,%7}, {%8,%9}, {%0,%1,%2,%3};"
        : "+f"(c[0]), "+f"(c[1]), "+f"(c[2]), "+f"(c[3])
        : "r"(a[0]), "r"(a[1]), "r"(a[2]), "r"(a[3]), "r"(b[0]), "r"(b[1]));
}

__device__ __forceinline__ float qmax(float v) {
    v = fmaxf(v, __shfl_xor_sync(0xffffffffu, v, 1));
    v = fmaxf(v, __shfl_xor_sync(0xffffffffu, v, 2));
    return v;
}
__device__ __forceinline__ float qsum(float v) {
    v += __shfl_xor_sync(0xffffffffu, v, 1);
    v += __shfl_xor_sync(0xffffffffu, v, 2);
    return v;
}

// ============================================================================
// Pre-pass kernels
// ============================================================================
__global__ __launch_bounds__(256) void round_tf32_vec(
    const float4* __restrict__ in, float4* __restrict__ out, int n4)
{
    int i = blockIdx.x * 256 + threadIdx.x;
    if (i < n4) {
        float4 v = in[i];
        v.x = tf32_rna(v.x); v.y = tf32_rna(v.y);
        v.z = tf32_rna(v.z); v.w = tf32_rna(v.w);
        out[i] = v;
    }
}

// WT[n][k] = round(W[k][n]); W is [K][N] row-major. block (32,8), grid (N/32, K/32)
__global__ __launch_bounds__(256) void transpose_tf32(
    const float* __restrict__ W, float* __restrict__ WT, int K, int N)
{
    __shared__ float t[32][33];
    int nb = blockIdx.x * 32, kb = blockIdx.y * 32;
    int x = threadIdx.x, y = threadIdx.y;
    #pragma unroll
    for (int i = 0; i < 32; i += 8)
        t[y + i][x] = W[(size_t)(kb + y + i) * N + nb + x];
    __syncthreads();
    #pragma unroll
    for (int i = 0; i < 32; i += 8)
        WT[(size_t)(nb + y + i) * K + kb + x] = tf32_rna(t[x][y + i]);
}

// ============================================================================
// mma.sync tf32 GEMM: C[M,N] = A[M,K] @ BT[N,K]^T (+bias)
// 128x128 tile, K-tile 32, 4 warps (64x64 each), 3-stage cp.async.
// A, BT pre-rounded to tf32. M%128==0, N%128==0, K%32==0.
// ============================================================================
#define G_AS_F   (128 * 36)
#define G_STAGE_F (2 * G_AS_F)
#define GEMM_SMEM (3 * G_STAGE_F * 4)

__global__ __launch_bounds__(128) void gemm_mma(
    const float* __restrict__ A, const float* __restrict__ BT,
    const float* __restrict__ bias, float* __restrict__ C,
    int M, int N, int K)
{
    extern __shared__ float smf[];
    const int tid = threadIdx.x;
    const int wid = tid >> 5, lane = tid & 31;
    const int g = lane >> 2, tg = lane & 3;
    const int wm = (wid >> 1) * 64, wn = (wid & 1) * 64;
    const int m0 = blockIdx.y * 128, n0 = blockIdx.x * 128;
    const int NK = K / 32;

    float c[4][8][4];
    #pragma unroll
    for (int mt = 0; mt < 4; mt++)
        #pragma unroll
        for (int nt = 0; nt < 8; nt++)
            #pragma unroll
            for (int i = 0; i < 4; i++) c[mt][nt][i] = 0.f;

    auto load_stage = [&](int ks) {
        float* As = smf + (ks % 3) * G_STAGE_F;
        float* Bs = As + G_AS_F;
        const float* Ap = A + (size_t)m0 * K + ks * 32;
        const float* Bp = BT + (size_t)n0 * K + ks * 32;
        #pragma unroll
        for (int i = 0; i < 8; i++) {
            int e = i * 128 + tid;
            int row = e >> 3, cc = e & 7;
            cp16(smem_u32(As + row * 36 + cc * 4), Ap + (size_t)row * K + cc * 4);
        }
        #pragma unroll
        for (int i = 0; i < 8; i++) {
            int e = i * 128 + tid;
            int row = e >> 3, cc = e & 7;
            cp16(smem_u32(Bs + row * 36 + cc * 4), Bp + (size_t)row * K + cc * 4);
        }
        cp_commit();
    };

    load_stage(0); load_stage(1); load_stage(2);

    for (int ks = 0; ks < NK; ks++) {
        cp_wait2();
        __syncthreads();
        const float* As = smf + (ks % 3) * G_STAGE_F;
        const float* Bs = As + G_AS_F;

        #pragma unroll
        for (int k8 = 0; k8 < 4; k8++) {
            const int k0 = k8 * 8;
            uint32_t af[4][4], bf[8][2];
            #pragma unroll
            for (int mt = 0; mt < 4; mt++) {
                int r = wm + mt * 16 + g;
                af[mt][0] = __float_as_uint(As[r * 36 + k0 + tg]);
                af[mt][1] = __float_as_uint(As[(r + 8) * 36 + k0 + tg]);
                af[mt][2] = __float_as_uint(As[r * 36 + k0 + tg + 4]);
                af[mt][3] = __float_as_uint(As[(r + 8) * 36 + k0 + tg + 4]);
            }
            #pragma unroll
            for (int nt = 0; nt < 8; nt++) {
                int r = wn + nt * 8 + g;
                bf[nt][0] = __float_as_uint(Bs[r * 36 + k0 + tg]);
                bf[nt][1] = __float_as_uint(Bs[r * 36 + k0 + tg + 4]);
            }
            #pragma unroll
            for (int mt = 0; mt < 4; mt++)
                #pragma unroll
                for (int nt = 0; nt < 8; nt++)
                    mma8(c[mt][nt], af[mt], bf[nt]);
        }
        __syncthreads();
        if (ks + 3 < NK) load_stage(ks + 3);
        else cp_commit();   // keep one commit per iteration so wait_group 2 pins stage ks
    }

    // Epilogue: direct stores from fragments (+bias)
    #pragma unroll
    for (int mt = 0; mt < 4; mt++) {
        int r0 = m0 + wm + mt * 16 + g;
        #pragma unroll
        for (int nt = 0; nt < 8; nt++) {
            int col = n0 + wn + nt * 8 + 2 * tg;
            float bx = 0.f, by = 0.f;
            if (bias) { bx = bias[col]; by = bias[col + 1]; }
            float2 v0 = { c[mt][nt][0] + bx, c[mt][nt][1] + by };
            float2 v1 = { c[mt][nt][2] + bx, c[mt][nt][3] + by };
            *(float2*)(C + (size_t)r0 * N + col) = v0;
            *(float2*)(C + (size_t)(r0 + 8) * N + col) = v1;
        }
    }
}

// ============================================================================
// Flash attention with mma.sync tf32.
// Block: 128 threads (4 warps), q-tile 128 (warp owns 32 q-rows = 2 m-tiles),
// k-tile 64. Grid (N/128, B*H).
// ============================================================================
#define FSTR 72
#define F_PS (128 * FSTR)
#define F_KS (F_PS + 128 * FSTR)
#define F_VS (F_KS + 64 * FSTR)
#define F_MK (F_VS + 64 * FSTR)
#define FLASH_SMEM ((F_MK + 64) * 4)

__global__ __launch_bounds__(128) void flash_mma(
    const float* __restrict__ qkv, const float* __restrict__ mask,
    float* __restrict__ ctx)
{
    extern __shared__ float smf[];
    float* Qs = smf;
    float* Ps = smf + F_PS;
    float* Ks = smf + F_KS;
    float* Vs = smf + F_VS;
    float* mks = smf + F_MK;

    const int tid = threadIdx.x;
    const int wid = tid >> 5, lane = tid & 31;
    const int g = lane >> 2, tg = lane & 3;
    const int b = blockIdx.y >> 4, h = blockIdx.y & 15;
    const int q0 = blockIdx.x * 128;

    const float* qb = qkv + (size_t)b * kN * 3 * kD + h * kHS;
    const float* kbp = qb + kD;
    const float* vbp = qb + 2 * kD;

    // Load Q tile (tf32-rounded), rows 0..127, cols 0..63
    #pragma unroll
    for (int i = 0; i < 16; i++) {
        int e = i * 128 + tid;
        int row = e >> 4, cc = (e & 15) * 4;
        float4 v = *(const float4*)(qb + (size_t)(q0 + row) * (3 * kD) + cc);
        v.x = tf32_rna(v.x); v.y = tf32_rna(v.y);
        v.z = tf32_rna(v.z); v.w = tf32_rna(v.w);
        *(float4*)(Qs + row * FSTR + cc) = v;
    }

    float mq[2][2];
    #pragma unroll
    for (int mt = 0; mt < 2; mt++) {
        int r = q0 + wid * 32 + mt * 16 + g;
        mq[mt][0] = mask[b * kN + r];
        mq[mt][1] = mask[b * kN + r + 8];
    }

    float m_[2][2], l_[2][2], o[2][8][4];
    #pragma unroll
    for (int mt = 0; mt < 2; mt++) {
        m_[mt][0] = -CUDART_INF_F; m_[mt][1] = -CUDART_INF_F;
        l_[mt][0] = 0.f; l_[mt][1] = 0.f;
        #pragma unroll
        for (int nt = 0; nt < 8; nt++)
            #pragma unroll
            for (int i = 0; i < 4; i++) o[mt][nt][i] = 0.f;
    }
    __syncthreads();

    for (int kt = 0; kt < kN / 64; kt++) {
        const int kb0 = kt * 64;
        __syncthreads();   // previous iteration's Ks/Vs/Ps reads complete
        #pragma unroll
        for (int i = 0; i < 8; i++) {
            int e = i * 128 + tid;
            int row = e >> 4, cc = (e & 15) * 4;
            float4 v = *(const float4*)(kbp + (size_t)(kb0 + row) * (3 * kD) + cc);
            v.x = tf32_rna(v.x); v.y = tf32_rna(v.y);
            v.z = tf32_rna(v.z); v.w = tf32_rna(v.w);
            *(float4*)(Ks + row * FSTR + cc) = v;
            float4 w = *(const float4*)(vbp + (size_t)(kb0 + row) * (3 * kD) + cc);
            w.x = tf32_rna(w.x); w.y = tf32_rna(w.y);
            w.z = tf32_rna(w.z); w.w = tf32_rna(w.w);
            *(float4*)(Vs + row * FSTR + cc) = w;
        }
        if (tid < 64) mks[tid] = mask[b * kN + kb0 + tid];
        __syncthreads();

        // ---- S = Q @ K^T ----
        float s[2][8][4];
        #pragma unroll
        for (int mt = 0; mt < 2; mt++)
            #pragma unroll
            for (int nt = 0; nt < 8; nt++)
                #pragma unroll
                for (int i = 0; i < 4; i++) s[mt][nt][i] = 0.f;

        #pragma unroll
        for (int k8 = 0; k8 < 8; k8++) {
            const int k0 = k8 * 8;
            uint32_t af[2][4];
            #pragma unroll
            for (int mt = 0; mt < 2; mt++) {
                int r = wid * 32 + mt * 16 + g;
                af[mt][0] = __float_as_uint(Qs[r * FSTR + k0 + tg]);
                af[mt][1] = __float_as_uint(Qs[(r + 8) * FSTR + k0 + tg]);
                af[mt][2] = __float_as_uint(Qs[r * FSTR + k0 + tg + 4]);
                af[mt][3] = __float_as_uint(Qs[(r + 8) * FSTR + k0 + tg + 4]);
            }
            #pragma unroll
            for (int nt = 0; nt < 8; nt++) {
                uint32_t bfr[2];
                int kr = nt * 8 + g;
                bfr[0] = __float_as_uint(Ks[kr * FSTR + k0 + tg]);
                bfr[1] = __float_as_uint(Ks[kr * FSTR + k0 + tg + 4]);
                mma8(s[0][nt], af[0], bfr);
                mma8(s[1][nt], af[1], bfr);
            }
        }

        // key masks for this thread's columns
        float mk0[8], mk1[8];
        #pragma unroll
        for (int nt = 0; nt < 8; nt++) {
            mk0[nt] = mks[nt * 8 + 2 * tg];
            mk1[nt] = mks[nt * 8 + 2 * tg + 1];
        }

        // ---- softmax (online) per m-tile ----
        #pragma unroll
        for (int mt = 0; mt < 2; mt++) {
            float tmA = -CUDART_INF_F, tmB = -CUDART_INF_F;
            #pragma unroll
            for (int nt = 0; nt < 8; nt++) {
                float v0 = (s[mt][nt][0] * SCALE) * (mq[mt][0] * mk0[nt]);
                float v1 = (s[mt][nt][1] * SCALE) * (mq[mt][0] * mk1[nt]);
                float v2 = (s[mt][nt][2] * SCALE) * (mq[mt][1] * mk0[nt]);
                float v3 = (s[mt][nt][3] * SCALE) * (mq[mt][1] * mk1[nt]);
                if (v0 == 0.f) v0 = -CUDART_INF_F;
                if (v1 == 0.f) v1 = -CUDART_INF_F;
                if (v2 == 0.f) v2 = -CUDART_INF_F;
                if (v3 == 0.f) v3 = -CUDART_INF_F;
                s[mt][nt][0] = v0; s[mt][nt][1] = v1;
                s[mt][nt][2] = v2; s[mt][nt][3] = v3;
                tmA = fmaxf(tmA, fmaxf(v0, v1));
                tmB = fmaxf(tmB, fmaxf(v2, v3));
            }
            tmA = qmax(tmA); tmB = qmax(tmB);
            float nmA = fmaxf(m_[mt][0], tmA);
            float nmB = fmaxf(m_[mt][1], tmB);
            float cA = (m_[mt][0] == -CUDART_INF_F) ? 0.f : __expf(m_[mt][0] - nmA);
            float cB = (m_[mt][1] == -CUDART_INF_F) ? 0.f : __expf(m_[mt][1] - nmB);
            float sA = 0.f, sB = 0.f;
            int r0 = wid * 32 + mt * 16 + g;
            #pragma unroll
            for (int nt = 0; nt < 8; nt++) {
                float p0 = (nmA == -CUDART_INF_F) ? 0.f : __expf(s[mt][nt][0] - nmA);
                float p1 = (nmA == -CUDART_INF_F) ? 0.f : __expf(s[mt][nt][1] - nmA);
                float p2 = (nmB == -CUDART_INF_F) ? 0.f : __expf(s[mt][nt][2] - nmB);
                float p3 = (nmB == -CUDART_INF_F) ? 0.f : __expf(s[mt][nt][3] - nmB);
                sA += p0 + p1; sB += p2 + p3;
                int cc = nt * 8 + 2 * tg;
                Ps[r0 * FSTR + cc]           = tf32_rna(p0);
                Ps[r0 * FSTR + cc + 1]       = tf32_rna(p1);
                Ps[(r0 + 8) * FSTR + cc]     = tf32_rna(p2);
                Ps[(r0 + 8) * FSTR + cc + 1] = tf32_rna(p3);
            }
            sA = qsum(sA); sB = qsum(sB);
            l_[mt][0] = l_[mt][0] * cA + sA;
            l_[mt][1] = l_[mt][1] * cB + sB;
            m_[mt][0] = nmA; m_[mt][1] = nmB;
            #pragma unroll
            for (int nt = 0; nt < 8; nt++) {
                o[mt][nt][0] *= cA; o[mt][nt][1] *= cA;
                o[mt][nt][2] *= cB; o[mt][nt][3] *= cB;
            }
        }
        __syncwarp();

        // ---- O += P @ V ----
        #pragma unroll
        for (int k8 = 0; k8 < 8; k8++) {
            const int k0 = k8 * 8;
            uint32_t pa[2][4];
            #pragma unroll
            for (int mt = 0; mt < 2; mt++) {
                int r = wid * 32 + mt * 16 + g;
                pa[mt][0] = __float_as_uint(Ps[r * FSTR + k0 + tg]);
                pa[mt][1] = __float_as_uint(Ps[(r + 8) * FSTR + k0 + tg]);
                pa[mt][2] = __float_as_uint(Ps[r * FSTR + k0 + tg + 4]);
                pa[mt][3] = __float_as_uint(Ps[(r + 8) * FSTR + k0 + tg + 4]);
            }
            #pragma unroll
            for (int nt = 0; nt < 8; nt++) {
                uint32_t bfr[2];
                bfr[0] = __float_as_uint(Vs[(k0 + tg) * FSTR + nt * 8 + g]);
                bfr[1] = __float_as_uint(Vs[(k0 + tg + 4) * FSTR + nt * 8 + g]);
                mma8(o[0][nt], pa[0], bfr);
                mma8(o[1][nt], pa[1], bfr);
            }
        }
    }

    // Epilogue: ctx = O / l, tf32-rounded (feeds tf32 out-projection)
    #pragma unroll
    for (int mt = 0; mt < 2; mt++) {
        float invA = 1.f / l_[mt][0];
        float invB = 1.f / l_[mt][1];
        int rg = b * kN + q0 + wid * 32 + mt * 16 + g;
        #pragma unroll
        for (int nt = 0; nt < 8; nt++) {
            int col = h * kHS + nt * 8 + 2 * tg;
            float2 v0 = { tf32_rna(o[mt][nt][0] * invA), tf32_rna(o[mt][nt][1] * invA) };
            float2 v1 = { tf32_rna(o[mt][nt][2] * invB), tf32_rna(o[mt][nt][3] * invB) };
            *(float2*)(ctx + (size_t)rg * kD + col) = v0;
            *(float2*)(ctx + (size_t)(rg + 8) * kD + col) = v1;
        }
    }
}

// ---------------------------------------------------------------------------
extern "C" void kernel_launch(void* const* d_in, const int* in_sizes, int n_in,
                              void* d_out, int out_size)
{
    const float* x         = (const float*)d_in[0];
    const float* attn_mask = (const float*)d_in[1];
    const float* Wqkv      = (const float*)d_in[2];
    const float* Wout      = (const float*)d_in[3];
    const float* bout      = (const float*)d_in[4];
    float* out = (float*)d_out;

    float *qkvbuf, *ctxbuf, *xr, *wqkvT, *woutT;
    cudaGetSymbolAddress((void**)&qkvbuf, g_qkv);
    cudaGetSymbolAddress((void**)&ctxbuf, g_ctx);
    cudaGetSymbolAddress((void**)&xr, g_xr);
    cudaGetSymbolAddress((void**)&wqkvT, g_wqkvT);
    cudaGetSymbolAddress((void**)&woutT, g_woutT);

    cudaFuncSetAttribute(gemm_mma, cudaFuncAttributeMaxDynamicSharedMemorySize,
                         GEMM_SMEM);
    cudaFuncSetAttribute(flash_mma, cudaFuncAttributeMaxDynamicSharedMemorySize,
                         FLASH_SMEM);

    // Pre-pass: round x to tf32; transpose+round weights
    {
        int n4 = kM * kD / 4;
        round_tf32_vec<<<(n4 + 255) / 256, 256>>>((const float4*)x, (float4*)xr, n4);
        transpose_tf32<<<dim3(3 * kD / 32, kD / 32), dim3(32, 8)>>>(Wqkv, wqkvT, kD, 3 * kD);
        transpose_tf32<<<dim3(kD / 32, kD / 32), dim3(32, 8)>>>(Wout, woutT, kD, kD);
    }

    // 1) qkv = x @ Wqkv
    gemm_mma<<<dim3(3 * kD / 128, kM / 128), 128, GEMM_SMEM>>>(
        xr, wqkvT, nullptr, qkvbuf, kM, 3 * kD, kD);

    // 2) attention
    flash_mma<<<dim3(kN / 128, kB * kH), 128, FLASH_SMEM>>>(
        qkvbuf, attn_mask, ctxbuf);

    // 3) out = ctx @ Wout + bout
    gemm_mma<<<dim3(kD / 128, kM / 128), 128, GEMM_SMEM>>>(
        ctxbuf, woutT, bout, out, kM, kD, kD);
}

// round 5
// speedup vs baseline: 3.1547x; 1.0295x over previous
#include <cuda_runtime.h>
#include <math_constants.h>
#include <cstdint>
#include <cstddef>

// Problem constants
#define kB  2
#define kN  2048
#define kD  1024
#define kH  16
#define kHS 64
#define kM  (kB * kN)        // 4096 rows
#define SCALE 0.03125f       // 1024^-0.5

// Scratch (allocation-free rule: __device__ globals)
__device__ float g_qkv[(size_t)kM * 3 * kD];    // (B*N, 3D) tf32-rounded
__device__ float g_ctx[(size_t)kM * kD];        // (B*N, D) tf32-rounded
__device__ float g_xr[(size_t)kM * kD];         // x rounded to tf32
__device__ float g_wqkvT[(size_t)3 * kD * kD];  // Wqkv^T [3D][D] tf32
__device__ float g_woutT[(size_t)kD * kD];      // Wout^T [D][D] tf32

// ============================================================================
// Helpers
// ============================================================================
__device__ __forceinline__ uint32_t smem_u32(const void* p) {
    uint32_t a;
    asm("{ .reg .u64 t; cvta.to.shared.u64 t, %1; cvt.u32.u64 %0, t; }"
        : "=r"(a) : "l"(p));
    return a;
}
__device__ __forceinline__ float tf32_rna(float x) {
    float r;
    asm("cvt.rna.tf32.f32 %0, %1;" : "=f"(r) : "f"(x));
    return r;
}
__device__ __forceinline__ void cp16(uint32_t dst, const void* src) {
    asm volatile("cp.async.cg.shared.global [%0], [%1], 16;" :: "r"(dst), "l"(src));
}
__device__ __forceinline__ void cp_commit() {
    asm volatile("cp.async.commit_group;" ::: "memory");
}
__device__ __forceinline__ void cp_wait0() {
    asm volatile("cp.async.wait_group 0;" ::: "memory");
}
__device__ __forceinline__ void cp_wait1() {
    asm volatile("cp.async.wait_group 1;" ::: "memory");
}
__device__ __forceinline__ void cp_wait2() {
    asm volatile("cp.async.wait_group 2;" ::: "memory");
}

// m16n8k8 tf32 mma, fp32 accumulate in-place
__device__ __forceinline__ void mma8(float* c, const uint32_t* a, const uint32_t* b) {
    asm volatile(
        "mma.sync.aligned.m16n8k8.row.col.f32.tf32.tf32.f32 "
        "{%0,%1,%2,%3}, {%4,%5,%6,%7}, {%8,%9}, {%0,%1,%2,%3};"
        : "+f"(c[0]), "+f"(c[1]), "+f"(c[2]), "+f"(c[3])
        : "r"(a[0]), "r"(a[1]), "r"(a[2]), "r"(a[3]), "r"(b[0]), "r"(b[1]));
}

__device__ __forceinline__ float qmax(float v) {
    v = fmaxf(v, __shfl_xor_sync(0xffffffffu, v, 1));
    v = fmaxf(v, __shfl_xor_sync(0xffffffffu, v, 2));
    return v;
}
__device__ __forceinline__ float qsum(float v) {
    v += __shfl_xor_sync(0xffffffffu, v, 1);
    v += __shfl_xor_sync(0xffffffffu, v, 2);
    return v;
}

// ============================================================================
// Pre-pass kernels
// ============================================================================
__global__ __launch_bounds__(256) void round_tf32_vec(
    const float4* __restrict__ in, float4* __restrict__ out, int n4)
{
    int i = blockIdx.x * 256 + threadIdx.x;
    if (i < n4) {
        float4 v = in[i];
        v.x = tf32_rna(v.x); v.y = tf32_rna(v.y);
        v.z = tf32_rna(v.z); v.w = tf32_rna(v.w);
        out[i] = v;
    }
}

// WT[n][k] = round(W[k][n]); W is [K][N] row-major. block (32,8), grid (N/32, K/32)
__global__ __launch_bounds__(256) void transpose_tf32(
    const float* __restrict__ W, float* __restrict__ WT, int K, int N)
{
    __shared__ float t[32][33];
    int nb = blockIdx.x * 32, kb = blockIdx.y * 32;
    int x = threadIdx.x, y = threadIdx.y;
    #pragma unroll
    for (int i = 0; i < 32; i += 8)
        t[y + i][x] = W[(size_t)(kb + y + i) * N + nb + x];
    __syncthreads();
    #pragma unroll
    for (int i = 0; i < 32; i += 8)
        WT[(size_t)(nb + y + i) * K + kb + x] = tf32_rna(t[x][y + i]);
}

// ============================================================================
// mma.sync tf32 GEMM: C[M,N] = A[M,K] @ BT[N,K]^T (+bias, optional tf32 round)
// Tile 128x256, K-tile 32, 8 warps (64x64 each), 3-stage cp.async, 256 thr.
// ============================================================================
#define G_AF   (128 * 36)
#define G_BF   (256 * 36)
#define G_STAGE_F (G_AF + G_BF)
#define GEMM_SMEM (3 * G_STAGE_F * 4)

__global__ __launch_bounds__(256) void gemm_mma(
    const float* __restrict__ A, const float* __restrict__ BT,
    const float* __restrict__ bias, float* __restrict__ C,
    int M, int N, int K, int round_out)
{
    extern __shared__ float smf[];
    const int tid = threadIdx.x;
    const int wid = tid >> 5, lane = tid & 31;
    const int g = lane >> 2, tg = lane & 3;
    const int wm = (wid >> 2) * 64, wn = (wid & 3) * 64;
    const int m0 = blockIdx.y * 128, n0 = blockIdx.x * 256;
    const int NK = K / 32;

    float c[4][8][4];
    #pragma unroll
    for (int mt = 0; mt < 4; mt++)
        #pragma unroll
        for (int nt = 0; nt < 8; nt++)
            #pragma unroll
            for (int i = 0; i < 4; i++) c[mt][nt][i] = 0.f;

    auto load_stage = [&](int ks) {
        float* As = smf + (ks % 3) * G_STAGE_F;
        float* Bs = As + G_AF;
        const float* Ap = A + (size_t)m0 * K + ks * 32;
        const float* Bp = BT + (size_t)n0 * K + ks * 32;
        #pragma unroll
        for (int i = 0; i < 4; i++) {
            int e = i * 256 + tid;
            int row = e >> 3, cc = e & 7;
            cp16(smem_u32(As + row * 36 + cc * 4), Ap + (size_t)row * K + cc * 4);
        }
        #pragma unroll
        for (int i = 0; i < 8; i++) {
            int e = i * 256 + tid;
            int row = e >> 3, cc = e & 7;
            cp16(smem_u32(Bs + row * 36 + cc * 4), Bp + (size_t)row * K + cc * 4);
        }
        cp_commit();
    };

    load_stage(0); load_stage(1); load_stage(2);

    for (int ks = 0; ks < NK; ks++) {
        cp_wait2();
        __syncthreads();
        const float* As = smf + (ks % 3) * G_STAGE_F;
        const float* Bs = As + G_AF;

        #pragma unroll
        for (int k8 = 0; k8 < 4; k8++) {
            const int k0 = k8 * 8;
            uint32_t af[4][4], bf[8][2];
            #pragma unroll
            for (int mt = 0; mt < 4; mt++) {
                int r = wm + mt * 16 + g;
                af[mt][0] = __float_as_uint(As[r * 36 + k0 + tg]);
                af[mt][1] = __float_as_uint(As[(r + 8) * 36 + k0 + tg]);
                af[mt][2] = __float_as_uint(As[r * 36 + k0 + tg + 4]);
                af[mt][3] = __float_as_uint(As[(r + 8) * 36 + k0 + tg + 4]);
            }
            #pragma unroll
            for (int nt = 0; nt < 8; nt++) {
                int r = wn + nt * 8 + g;
                bf[nt][0] = __float_as_uint(Bs[r * 36 + k0 + tg]);
                bf[nt][1] = __float_as_uint(Bs[r * 36 + k0 + tg + 4]);
            }
            #pragma unroll
            for (int mt = 0; mt < 4; mt++)
                #pragma unroll
                for (int nt = 0; nt < 8; nt++)
                    mma8(c[mt][nt], af[mt], bf[nt]);
        }
        __syncthreads();
        if (ks + 3 < NK) load_stage(ks + 3);
        else cp_commit();   // keep group count aligned so wait_group 2 pins stage ks
    }

    // Epilogue: direct fragment stores (+bias, optional tf32 rounding)
    #pragma unroll
    for (int mt = 0; mt < 4; mt++) {
        int r0 = m0 + wm + mt * 16 + g;
        #pragma unroll
        for (int nt = 0; nt < 8; nt++) {
            int col = n0 + wn + nt * 8 + 2 * tg;
            float bx = 0.f, by = 0.f;
            if (bias) { bx = bias[col]; by = bias[col + 1]; }
            float2 v0 = { c[mt][nt][0] + bx, c[mt][nt][1] + by };
            float2 v1 = { c[mt][nt][2] + bx, c[mt][nt][3] + by };
            if (round_out) {
                v0.x = tf32_rna(v0.x); v0.y = tf32_rna(v0.y);
                v1.x = tf32_rna(v1.x); v1.y = tf32_rna(v1.y);
            }
            *(float2*)(C + (size_t)r0 * N + col) = v0;
            *(float2*)(C + (size_t)(r0 + 8) * N + col) = v1;
        }
    }
}

// ============================================================================
// Flash attention, mma.sync tf32, q-tile 256, 8 warps, cp.async double-buffer.
// qkv must be pre-rounded to tf32. Grid (kN/256, B*H).
// Strides: Q/P/K = 68 (conflict-free A/B frag reads), V = 72 (conflict-free
// column-major B frag reads).
// ============================================================================
#define QSTR 68
#define KSTR 68
#define VSTR 72
#define F_Q  0
#define F_P  (F_Q + 256 * QSTR)
#define F_K  (F_P + 256 * QSTR)
#define F_V  (F_K + 2 * 64 * KSTR)
#define FLASH_SMEM ((F_V + 2 * 64 * VSTR) * 4)

__global__ __launch_bounds__(256) void flash_mma(
    const float* __restrict__ qkv, const float* __restrict__ mask,
    float* __restrict__ ctx)
{
    extern __shared__ float smf[];
    float* Qs = smf + F_Q;
    float* Ps = smf + F_P;

    const int tid = threadIdx.x;
    const int wid = tid >> 5, lane = tid & 31;
    const int g = lane >> 2, tg = lane & 3;
    const int b = blockIdx.y >> 4, h = blockIdx.y & 15;
    const int q0 = blockIdx.x * 256;
    const int NT = kN / 64;

    const float* qb = qkv + (size_t)b * kN * 3 * kD + h * kHS;
    const float* kbp = qb + kD;
    const float* vbp = qb + 2 * kD;
    const float* mrow = mask + b * kN;

    auto load_kv = [&](int kt) {
        const int st = kt & 1;
        float* Ks = smf + F_K + st * 64 * KSTR;
        float* Vs = smf + F_V + st * 64 * VSTR;
        const float* kp = kbp + (size_t)(kt * 64) * (3 * kD);
        const float* vp = vbp + (size_t)(kt * 64) * (3 * kD);
        #pragma unroll
        for (int i = 0; i < 4; i++) {
            int e = i * 256 + tid;
            int row = e >> 4, cc = (e & 15) * 4;
            cp16(smem_u32(Ks + row * KSTR + cc), kp + (size_t)row * (3 * kD) + cc);
            cp16(smem_u32(Vs + row * VSTR + cc), vp + (size_t)row * (3 * kD) + cc);
        }
        cp_commit();
    };

    // Q tile (256 rows x 64) + first K/V stage, one group
    #pragma unroll
    for (int i = 0; i < 16; i++) {
        int e = i * 256 + tid;
        int row = e >> 4, cc = (e & 15) * 4;
        cp16(smem_u32(Qs + row * QSTR + cc), qb + (size_t)(q0 + row) * (3 * kD) + cc);
    }
    load_kv(0);

    float mq[2][2];
    #pragma unroll
    for (int mt = 0; mt < 2; mt++) {
        int r = q0 + wid * 32 + mt * 16 + g;
        mq[mt][0] = mrow[r];
        mq[mt][1] = mrow[r + 8];
    }

    float m_[2][2], l_[2][2], o[2][8][4];
    #pragma unroll
    for (int mt = 0; mt < 2; mt++) {
        m_[mt][0] = -CUDART_INF_F; m_[mt][1] = -CUDART_INF_F;
        l_[mt][0] = 0.f; l_[mt][1] = 0.f;
        #pragma unroll
        for (int nt = 0; nt < 8; nt++)
            #pragma unroll
            for (int i = 0; i < 4; i++) o[mt][nt][i] = 0.f;
    }

    for (int kt = 0; kt < NT; kt++) {
        if (kt + 1 < NT) { load_kv(kt + 1); cp_wait1(); }
        else cp_wait0();
        __syncthreads();

        const int st = kt & 1;
        const float* Ks = smf + F_K + st * 64 * KSTR;
        const float* Vs = smf + F_V + st * 64 * VSTR;
        const int kb0 = kt * 64;

        // ---- S = Q @ K^T ----
        float s[2][8][4];
        #pragma unroll
        for (int mt = 0; mt < 2; mt++)
            #pragma unroll
            for (int nt = 0; nt < 8; nt++)
                #pragma unroll
                for (int i = 0; i < 4; i++) s[mt][nt][i] = 0.f;

        #pragma unroll
        for (int k8 = 0; k8 < 8; k8++) {
            const int k0 = k8 * 8;
            uint32_t af[2][4];
            #pragma unroll
            for (int mt = 0; mt < 2; mt++) {
                int r = wid * 32 + mt * 16 + g;
                af[mt][0] = __float_as_uint(Qs[r * QSTR + k0 + tg]);
                af[mt][1] = __float_as_uint(Qs[(r + 8) * QSTR + k0 + tg]);
                af[mt][2] = __float_as_uint(Qs[r * QSTR + k0 + tg + 4]);
                af[mt][3] = __float_as_uint(Qs[(r + 8) * QSTR + k0 + tg + 4]);
            }
            #pragma unroll
            for (int nt = 0; nt < 8; nt++) {
                uint32_t bfr[2];
                int kr = nt * 8 + g;
                bfr[0] = __float_as_uint(Ks[kr * KSTR + k0 + tg]);
                bfr[1] = __float_as_uint(Ks[kr * KSTR + k0 + tg + 4]);
                mma8(s[0][nt], af[0], bfr);
                mma8(s[1][nt], af[1], bfr);
            }
        }

        // key masks for this thread's columns (gmem, L1-resident)
        float mk0[8], mk1[8];
        #pragma unroll
        for (int nt = 0; nt < 8; nt++) {
            mk0[nt] = mrow[kb0 + nt * 8 + 2 * tg];
            mk1[nt] = mrow[kb0 + nt * 8 + 2 * tg + 1];
        }

        // ---- softmax (online) per m-tile ----
        #pragma unroll
        for (int mt = 0; mt < 2; mt++) {
            float tmA = -CUDART_INF_F, tmB = -CUDART_INF_F;
            #pragma unroll
            for (int nt = 0; nt < 8; nt++) {
                float v0 = (s[mt][nt][0] * SCALE) * (mq[mt][0] * mk0[nt]);
                float v1 = (s[mt][nt][1] * SCALE) * (mq[mt][0] * mk1[nt]);
                float v2 = (s[mt][nt][2] * SCALE) * (mq[mt][1] * mk0[nt]);
                float v3 = (s[mt][nt][3] * SCALE) * (mq[mt][1] * mk1[nt]);
                if (v0 == 0.f) v0 = -CUDART_INF_F;
                if (v1 == 0.f) v1 = -CUDART_INF_F;
                if (v2 == 0.f) v2 = -CUDART_INF_F;
                if (v3 == 0.f) v3 = -CUDART_INF_F;
                s[mt][nt][0] = v0; s[mt][nt][1] = v1;
                s[mt][nt][2] = v2; s[mt][nt][3] = v3;
                tmA = fmaxf(tmA, fmaxf(v0, v1));
                tmB = fmaxf(tmB, fmaxf(v2, v3));
            }
            tmA = qmax(tmA); tmB = qmax(tmB);
            float nmA = fmaxf(m_[mt][0], tmA);
            float nmB = fmaxf(m_[mt][1], tmB);
            float cA = (m_[mt][0] == -CUDART_INF_F) ? 0.f : __expf(m_[mt][0] - nmA);
            float cB = (m_[mt][1] == -CUDART_INF_F) ? 0.f : __expf(m_[mt][1] - nmB);
            float sA = 0.f, sB = 0.f;
            int r0 = wid * 32 + mt * 16 + g;
            #pragma unroll
            for (int nt = 0; nt < 8; nt++) {
                float p0 = (nmA == -CUDART_INF_F) ? 0.f : __expf(s[mt][nt][0] - nmA);
                float p1 = (nmA == -CUDART_INF_F) ? 0.f : __expf(s[mt][nt][1] - nmA);
                float p2 = (nmB == -CUDART_INF_F) ? 0.f : __expf(s[mt][nt][2] - nmB);
                float p3 = (nmB == -CUDART_INF_F) ? 0.f : __expf(s[mt][nt][3] - nmB);
                sA += p0 + p1; sB += p2 + p3;
                int cc = nt * 8 + 2 * tg;
                Ps[r0 * QSTR + cc]           = tf32_rna(p0);
                Ps[r0 * QSTR + cc + 1]       = tf32_rna(p1);
                Ps[(r0 + 8) * QSTR + cc]     = tf32_rna(p2);
                Ps[(r0 + 8) * QSTR + cc + 1] = tf32_rna(p3);
            }
            sA = qsum(sA); sB = qsum(sB);
            l_[mt][0] = l_[mt][0] * cA + sA;
            l_[mt][1] = l_[mt][1] * cB + sB;
            m_[mt][0] = nmA; m_[mt][1] = nmB;
            #pragma unroll
            for (int nt = 0; nt < 8; nt++) {
                o[mt][nt][0] *= cA; o[mt][nt][1] *= cA;
                o[mt][nt][2] *= cB; o[mt][nt][3] *= cB;
            }
        }
        __syncwarp();

        // ---- O += P @ V ----
        #pragma unroll
        for (int k8 = 0; k8 < 8; k8++) {
            const int k0 = k8 * 8;
            uint32_t pa[2][4];
            #pragma unroll
            for (int mt = 0; mt < 2; mt++) {
                int r = wid * 32 + mt * 16 + g;
                pa[mt][0] = __float_as_uint(Ps[r * QSTR + k0 + tg]);
                pa[mt][1] = __float_as_uint(Ps[(r + 8) * QSTR + k0 + tg]);
                pa[mt][2] = __float_as_uint(Ps[r * QSTR + k0 + tg + 4]);
                pa[mt][3] = __float_as_uint(Ps[(r + 8) * QSTR + k0 + tg + 4]);
            }
            #pragma unroll
            for (int nt = 0; nt < 8; nt++) {
                uint32_t bfr[2];
                bfr[0] = __float_as_uint(Vs[(k0 + tg) * VSTR + nt * 8 + g]);
                bfr[1] = __float_as_uint(Vs[(k0 + tg + 4) * VSTR + nt * 8 + g]);
                mma8(o[0][nt], pa[0], bfr);
                mma8(o[1][nt], pa[1], bfr);
            }
        }
        __syncthreads();   // all warps done with stage kt before it is reloaded
    }

    // Epilogue: ctx = O / l, tf32-rounded (feeds tf32 out-projection)
    #pragma unroll
    for (int mt = 0; mt < 2; mt++) {
        float invA = 1.f / l_[mt][0];
        float invB = 1.f / l_[mt][1];
        int rg = b * kN + q0 + wid * 32 + mt * 16 + g;
        #pragma unroll
        for (int nt = 0; nt < 8; nt++) {
            int col = h * kHS + nt * 8 + 2 * tg;
            float2 v0 = { tf32_rna(o[mt][nt][0] * invA), tf32_rna(o[mt][nt][1] * invA) };
            float2 v1 = { tf32_rna(o[mt][nt][2] * invB), tf32_rna(o[mt][nt][3] * invB) };
            *(float2*)(ctx + (size_t)rg * kD + col) = v0;
            *(float2*)(ctx + (size_t)(rg + 8) * kD + col) = v1;
        }
    }
}

// ---------------------------------------------------------------------------
extern "C" void kernel_launch(void* const* d_in, const int* in_sizes, int n_in,
                              void* d_out, int out_size)
{
    const float* x         = (const float*)d_in[0];
    const float* attn_mask = (const float*)d_in[1];
    const float* Wqkv      = (const float*)d_in[2];
    const float* Wout      = (const float*)d_in[3];
    const float* bout      = (const float*)d_in[4];
    float* out = (float*)d_out;

    float *qkvbuf, *ctxbuf, *xr, *wqkvT, *woutT;
    cudaGetSymbolAddress((void**)&qkvbuf, g_qkv);
    cudaGetSymbolAddress((void**)&ctxbuf, g_ctx);
    cudaGetSymbolAddress((void**)&xr, g_xr);
    cudaGetSymbolAddress((void**)&wqkvT, g_wqkvT);
    cudaGetSymbolAddress((void**)&woutT, g_woutT);

    cudaFuncSetAttribute(gemm_mma, cudaFuncAttributeMaxDynamicSharedMemorySize,
                         GEMM_SMEM);
    cudaFuncSetAttribute(flash_mma, cudaFuncAttributeMaxDynamicSharedMemorySize,
                         FLASH_SMEM);

    // Pre-pass: round x to tf32; transpose+round weights
    {
        int n4 = kM * kD / 4;
        round_tf32_vec<<<(n4 + 255) / 256, 256>>>((const float4*)x, (float4*)xr, n4);
        transpose_tf32<<<dim3(3 * kD / 32, kD / 32), dim3(32, 8)>>>(Wqkv, wqkvT, kD, 3 * kD);
        transpose_tf32<<<dim3(kD / 32, kD / 32), dim3(32, 8)>>>(Wout, woutT, kD, kD);
    }

    // 1) qkv = x @ Wqkv, output tf32-rounded (feeds flash)
    gemm_mma<<<dim3(3 * kD / 256, kM / 128), 256, GEMM_SMEM>>>(
        xr, wqkvT, nullptr, qkvbuf, kM, 3 * kD, kD, 1);

    // 2) attention
    flash_mma<<<dim3(kN / 256, kB * kH), 256, FLASH_SMEM>>>(
        qkvbuf, attn_mask, ctxbuf);

    // 3) out = ctx @ Wout + bout (full fp32 output)
    gemm_mma<<<dim3(kD / 256, kM / 128), 256, GEMM_SMEM>>>(
        ctxbuf, woutT, bout, out, kM, kD, kD, 0);
}

// round 6
// speedup vs baseline: 3.2754x; 1.0383x over previous
#include <cuda_runtime.h>
#include <math_constants.h>
#include <cstdint>
#include <cstddef>

// Problem constants
#define kB  2
#define kN  2048
#define kD  1024
#define kH  16
#define kHS 64
#define kM  (kB * kN)        // 4096 rows
// scale folded with log2(e): softmax computed in exp2 domain
#define SCALE2 0.045084220027780106f   // 1024^-0.5 * log2(e)

// Scratch (allocation-free rule: __device__ globals)
__device__ float g_qkv[(size_t)kM * 3 * kD];    // (B*N, 3D) tf32-rounded
__device__ float g_ctx[(size_t)kM * kD];        // (B*N, D) tf32-rounded
__device__ float g_xr[(size_t)kM * kD];         // x rounded to tf32
__device__ float g_wqkvT[(size_t)3 * kD * kD];  // Wqkv^T [3D][D] tf32
__device__ float g_woutT[(size_t)kD * kD];      // Wout^T [D][D] tf32

// ============================================================================
// Helpers
// ============================================================================
__device__ __forceinline__ uint32_t smem_u32(const void* p) {
    uint32_t a;
    asm("{ .reg .u64 t; cvta.to.shared.u64 t, %1; cvt.u32.u64 %0, t; }"
        : "=r"(a) : "l"(p));
    return a;
}
__device__ __forceinline__ float tf32_rna(float x) {
    float r;
    asm("cvt.rna.tf32.f32 %0, %1;" : "=f"(r) : "f"(x));
    return r;
}
__device__ __forceinline__ float ex2f(float x) {
    float r;
    asm("ex2.approx.f32 %0, %1;" : "=f"(r) : "f"(x));
    return r;
}
__device__ __forceinline__ void cp16(uint32_t dst, const void* src) {
    asm volatile("cp.async.cg.shared.global [%0], [%1], 16;" :: "r"(dst), "l"(src));
}
__device__ __forceinline__ void cp_commit() {
    asm volatile("cp.async.commit_group;" ::: "memory");
}
__device__ __forceinline__ void cp_wait0() {
    asm volatile("cp.async.wait_group 0;" ::: "memory");
}
__device__ __forceinline__ void cp_wait1() {
    asm volatile("cp.async.wait_group 1;" ::: "memory");
}

// m16n8k8 tf32 mma, fp32 accumulate in-place
__device__ __forceinline__ void mma8(float* c, const uint32_t* a, const uint32_t* b) {
    asm volatile(
        "mma.sync.aligned.m16n8k8.row.col.f32.tf32.tf32.f32 "
        "{%0,%1,%2,%3}, {%4,%5,%6,%7}, {%8,%9}, {%0,%1,%2,%3};"
        : "+f"(c[0]), "+f"(c[1]), "+f"(c[2]), "+f"(c[3])
        : "r"(a[0]), "r"(a[1]), "r"(a[2]), "r"(a[3]), "r"(b[0]), "r"(b[1]));
}

__device__ __forceinline__ float qmax(float v) {
    v = fmaxf(v, __shfl_xor_sync(0xffffffffu, v, 1));
    v = fmaxf(v, __shfl_xor_sync(0xffffffffu, v, 2));
    return v;
}
__device__ __forceinline__ float qsum(float v) {
    v += __shfl_xor_sync(0xffffffffu, v, 1);
    v += __shfl_xor_sync(0xffffffffu, v, 2);
    return v;
}

// ============================================================================
// Pre-pass kernels
// ============================================================================
__global__ __launch_bounds__(256) void round_tf32_vec(
    const float4* __restrict__ in, float4* __restrict__ out, int n4)
{
    int i = blockIdx.x * 256 + threadIdx.x;
    if (i < n4) {
        float4 v = in[i];
        v.x = tf32_rna(v.x); v.y = tf32_rna(v.y);
        v.z = tf32_rna(v.z); v.w = tf32_rna(v.w);
        out[i] = v;
    }
}

// WT[n][k] = round(W[k][n]); W is [K][N] row-major. block (32,8), grid (N/32, K/32)
__global__ __launch_bounds__(256) void transpose_tf32(
    const float* __restrict__ W, float* __restrict__ WT, int K, int N)
{
    __shared__ float t[32][33];
    int nb = blockIdx.x * 32, kb = blockIdx.y * 32;
    int x = threadIdx.x, y = threadIdx.y;
    #pragma unroll
    for (int i = 0; i < 32; i += 8)
        t[y + i][x] = W[(size_t)(kb + y + i) * N + nb + x];
    __syncthreads();
    #pragma unroll
    for (int i = 0; i < 32; i += 8)
        WT[(size_t)(nb + y + i) * K + kb + x] = tf32_rna(t[x][y + i]);
}

// ============================================================================
// mma.sync tf32 GEMM: C[M,N] = A[M,K] @ BT[N,K]^T (+bias, optional tf32 round)
// Tile 128x256, K-tile 64, 8 warps (64x64 each), 2-stage cp.async, 256 thr.
// ============================================================================
#define GSTR 68
#define G_AF   (128 * GSTR)
#define G_BF   (256 * GSTR)
#define G_STAGE_F (G_AF + G_BF)
#define GEMM_SMEM (2 * G_STAGE_F * 4)

__global__ __launch_bounds__(256) void gemm_mma(
    const float* __restrict__ A, const float* __restrict__ BT,
    const float* __restrict__ bias, float* __restrict__ C,
    int M, int N, int K, int round_out)
{
    extern __shared__ float smf[];
    const int tid = threadIdx.x;
    const int wid = tid >> 5, lane = tid & 31;
    const int g = lane >> 2, tg = lane & 3;
    const int wm = (wid >> 2) * 64, wn = (wid & 3) * 64;
    const int m0 = blockIdx.y * 128, n0 = blockIdx.x * 256;
    const int NK = K / 64;

    float c[4][8][4];
    #pragma unroll
    for (int mt = 0; mt < 4; mt++)
        #pragma unroll
        for (int nt = 0; nt < 8; nt++)
            #pragma unroll
            for (int i = 0; i < 4; i++) c[mt][nt][i] = 0.f;

    auto load_stage = [&](int ks) {
        float* As = smf + (ks & 1) * G_STAGE_F;
        float* Bs = As + G_AF;
        const float* Ap = A + (size_t)m0 * K + ks * 64;
        const float* Bp = BT + (size_t)n0 * K + ks * 64;
        #pragma unroll
        for (int i = 0; i < 8; i++) {
            int e = i * 256 + tid;
            int row = e >> 4, cc = e & 15;
            cp16(smem_u32(As + row * GSTR + cc * 4), Ap + (size_t)row * K + cc * 4);
        }
        #pragma unroll
        for (int i = 0; i < 16; i++) {
            int e = i * 256 + tid;
            int row = e >> 4, cc = e & 15;
            cp16(smem_u32(Bs + row * GSTR + cc * 4), Bp + (size_t)row * K + cc * 4);
        }
        cp_commit();
    };

    load_stage(0); load_stage(1);

    for (int ks = 0; ks < NK; ks++) {
        if (ks + 1 < NK) cp_wait1(); else cp_wait0();
        __syncthreads();
        const float* As = smf + (ks & 1) * G_STAGE_F;
        const float* Bs = As + G_AF;

        #pragma unroll
        for (int k8 = 0; k8 < 8; k8++) {
            const int k0 = k8 * 8;
            uint32_t af[4][4], bf[8][2];
            #pragma unroll
            for (int mt = 0; mt < 4; mt++) {
                int r = wm + mt * 16 + g;
                af[mt][0] = __float_as_uint(As[r * GSTR + k0 + tg]);
                af[mt][1] = __float_as_uint(As[(r + 8) * GSTR + k0 + tg]);
                af[mt][2] = __float_as_uint(As[r * GSTR + k0 + tg + 4]);
                af[mt][3] = __float_as_uint(As[(r + 8) * GSTR + k0 + tg + 4]);
            }
            #pragma unroll
            for (int nt = 0; nt < 8; nt++) {
                int r = wn + nt * 8 + g;
                bf[nt][0] = __float_as_uint(Bs[r * GSTR + k0 + tg]);
                bf[nt][1] = __float_as_uint(Bs[r * GSTR + k0 + tg + 4]);
            }
            #pragma unroll
            for (int mt = 0; mt < 4; mt++)
                #pragma unroll
                for (int nt = 0; nt < 8; nt++)
                    mma8(c[mt][nt], af[mt], bf[nt]);
        }
        __syncthreads();
        if (ks + 2 < NK) load_stage(ks + 2);
    }

    // Epilogue: direct fragment stores (+bias, optional tf32 rounding)
    #pragma unroll
    for (int mt = 0; mt < 4; mt++) {
        int r0 = m0 + wm + mt * 16 + g;
        #pragma unroll
        for (int nt = 0; nt < 8; nt++) {
            int col = n0 + wn + nt * 8 + 2 * tg;
            float bx = 0.f, by = 0.f;
            if (bias) { bx = bias[col]; by = bias[col + 1]; }
            float2 v0 = { c[mt][nt][0] + bx, c[mt][nt][1] + by };
            float2 v1 = { c[mt][nt][2] + bx, c[mt][nt][3] + by };
            if (round_out) {
                v0.x = tf32_rna(v0.x); v0.y = tf32_rna(v0.y);
                v1.x = tf32_rna(v1.x); v1.y = tf32_rna(v1.y);
            }
            *(float2*)(C + (size_t)r0 * N + col) = v0;
            *(float2*)(C + (size_t)(r0 + 8) * N + col) = v1;
        }
    }
}

// ============================================================================
// Flash attention, mma.sync tf32. q-tile 128, 4 warps (128 thr), 2 CTAs/SM.
// Q held in registers; K/V cp.async double-buffered; P staged via smem.
// qkv must be pre-rounded to tf32. Grid (kN/128, B*H).
// ============================================================================
#define PSTR 68
#define KSTR 68
#define VSTR 72
#define F_P  0
#define F_K  (F_P + 128 * PSTR)
#define F_V  (F_K + 2 * 64 * KSTR)
#define FLASH_SMEM ((F_V + 2 * 64 * VSTR) * 4)

__global__ __launch_bounds__(128, 2) void flash_mma(
    const float* __restrict__ qkv, const float* __restrict__ mask,
    float* __restrict__ ctx)
{
    extern __shared__ float smf[];
    float* Ps = smf + F_P;

    const int tid = threadIdx.x;
    const int wid = tid >> 5, lane = tid & 31;
    const int g = lane >> 2, tg = lane & 3;
    const int b = blockIdx.y >> 4, h = blockIdx.y & 15;
    const int q0 = blockIdx.x * 128;
    const int NT = kN / 64;

    const float* qb = qkv + (size_t)b * kN * 3 * kD + h * kHS;
    const float* kbp = qb + kD;
    const float* vbp = qb + 2 * kD;
    const float* mrow = mask + b * kN;

    auto load_kv = [&](int kt) {
        const int st = kt & 1;
        float* Ks = smf + F_K + st * 64 * KSTR;
        float* Vs = smf + F_V + st * 64 * VSTR;
        const float* kp = kbp + (size_t)(kt * 64) * (3 * kD);
        const float* vp = vbp + (size_t)(kt * 64) * (3 * kD);
        #pragma unroll
        for (int i = 0; i < 8; i++) {
            int e = i * 128 + tid;
            int row = e >> 4, cc = (e & 15) * 4;
            cp16(smem_u32(Ks + row * KSTR + cc), kp + (size_t)row * (3 * kD) + cc);
            cp16(smem_u32(Vs + row * VSTR + cc), vp + (size_t)row * (3 * kD) + cc);
        }
        cp_commit();
    };

    load_kv(0);

    // Q tile into registers, fragment layout: qf[k8][mt][4]
    float qf[8][2][4];
    #pragma unroll
    for (int mt = 0; mt < 2; mt++) {
        const float* r0p = qb + (size_t)(q0 + wid * 32 + mt * 16 + g) * (3 * kD);
        const float* r8p = r0p + (size_t)8 * (3 * kD);
        #pragma unroll
        for (int k8 = 0; k8 < 8; k8++) {
            qf[k8][mt][0] = r0p[k8 * 8 + tg];
            qf[k8][mt][1] = r8p[k8 * 8 + tg];
            qf[k8][mt][2] = r0p[k8 * 8 + tg + 4];
            qf[k8][mt][3] = r8p[k8 * 8 + tg + 4];
        }
    }

    float mq[2][2];
    #pragma unroll
    for (int mt = 0; mt < 2; mt++) {
        int r = q0 + wid * 32 + mt * 16 + g;
        mq[mt][0] = mrow[r];
        mq[mt][1] = mrow[r + 8];
    }

    float m_[2][2], l_[2][2], o[2][8][4];
    #pragma unroll
    for (int mt = 0; mt < 2; mt++) {
        m_[mt][0] = -CUDART_INF_F; m_[mt][1] = -CUDART_INF_F;
        l_[mt][0] = 0.f; l_[mt][1] = 0.f;
        #pragma unroll
        for (int nt = 0; nt < 8; nt++)
            #pragma unroll
            for (int i = 0; i < 4; i++) o[mt][nt][i] = 0.f;
    }

    for (int kt = 0; kt < NT; kt++) {
        if (kt + 1 < NT) { load_kv(kt + 1); cp_wait1(); }
        else cp_wait0();
        __syncthreads();

        const int st = kt & 1;
        const float* Ks = smf + F_K + st * 64 * KSTR;
        const float* Vs = smf + F_V + st * 64 * VSTR;
        const int kb0 = kt * 64;

        // ---- S = Q @ K^T ----
        float s[2][8][4];
        #pragma unroll
        for (int mt = 0; mt < 2; mt++)
            #pragma unroll
            for (int nt = 0; nt < 8; nt++)
                #pragma unroll
                for (int i = 0; i < 4; i++) s[mt][nt][i] = 0.f;

        #pragma unroll
        for (int k8 = 0; k8 < 8; k8++) {
            const int k0 = k8 * 8;
            uint32_t af[2][4];
            #pragma unroll
            for (int mt = 0; mt < 2; mt++) {
                af[mt][0] = __float_as_uint(qf[k8][mt][0]);
                af[mt][1] = __float_as_uint(qf[k8][mt][1]);
                af[mt][2] = __float_as_uint(qf[k8][mt][2]);
                af[mt][3] = __float_as_uint(qf[k8][mt][3]);
            }
            #pragma unroll
            for (int nt = 0; nt < 8; nt++) {
                uint32_t bfr[2];
                int kr = nt * 8 + g;
                bfr[0] = __float_as_uint(Ks[kr * KSTR + k0 + tg]);
                bfr[1] = __float_as_uint(Ks[kr * KSTR + k0 + tg + 4]);
                mma8(s[0][nt], af[0], bfr);
                mma8(s[1][nt], af[1], bfr);
            }
        }

        // key masks for this thread's columns
        float mk0[8], mk1[8];
        #pragma unroll
        for (int nt = 0; nt < 8; nt++) {
            mk0[nt] = mrow[kb0 + nt * 8 + 2 * tg];
            mk1[nt] = mrow[kb0 + nt * 8 + 2 * tg + 1];
        }

        // ---- online softmax (exp2 domain) ----
        #pragma unroll
        for (int mt = 0; mt < 2; mt++) {
            float tmA = -CUDART_INF_F, tmB = -CUDART_INF_F;
            #pragma unroll
            for (int nt = 0; nt < 8; nt++) {
                float v0 = (s[mt][nt][0] * SCALE2) * (mq[mt][0] * mk0[nt]);
                float v1 = (s[mt][nt][1] * SCALE2) * (mq[mt][0] * mk1[nt]);
                float v2 = (s[mt][nt][2] * SCALE2) * (mq[mt][1] * mk0[nt]);
                float v3 = (s[mt][nt][3] * SCALE2) * (mq[mt][1] * mk1[nt]);
                if (v0 == 0.f) v0 = -CUDART_INF_F;
                if (v1 == 0.f) v1 = -CUDART_INF_F;
                if (v2 == 0.f) v2 = -CUDART_INF_F;
                if (v3 == 0.f) v3 = -CUDART_INF_F;
                s[mt][nt][0] = v0; s[mt][nt][1] = v1;
                s[mt][nt][2] = v2; s[mt][nt][3] = v3;
                tmA = fmaxf(tmA, fmaxf(v0, v1));
                tmB = fmaxf(tmB, fmaxf(v2, v3));
            }
            tmA = qmax(tmA); tmB = qmax(tmB);
            float nmA = fmaxf(m_[mt][0], tmA);
            float nmB = fmaxf(m_[mt][1], tmB);
            float cA = (m_[mt][0] == -CUDART_INF_F) ? 0.f : ex2f(m_[mt][0] - nmA);
            float cB = (m_[mt][1] == -CUDART_INF_F) ? 0.f : ex2f(m_[mt][1] - nmB);
            float sA = 0.f, sB = 0.f;
            int r0 = wid * 32 + mt * 16 + g;
            #pragma unroll
            for (int nt = 0; nt < 8; nt++) {
                float p0 = (nmA == -CUDART_INF_F) ? 0.f : ex2f(s[mt][nt][0] - nmA);
                float p1 = (nmA == -CUDART_INF_F) ? 0.f : ex2f(s[mt][nt][1] - nmA);
                float p2 = (nmB == -CUDART_INF_F) ? 0.f : ex2f(s[mt][nt][2] - nmB);
                float p3 = (nmB == -CUDART_INF_F) ? 0.f : ex2f(s[mt][nt][3] - nmB);
                sA += p0 + p1; sB += p2 + p3;
                int cc = nt * 8 + 2 * tg;
                float2 w0 = { tf32_rna(p0), tf32_rna(p1) };
                float2 w1 = { tf32_rna(p2), tf32_rna(p3) };
                *(float2*)&Ps[r0 * PSTR + cc] = w0;
                *(float2*)&Ps[(r0 + 8) * PSTR + cc] = w1;
            }
            sA = qsum(sA); sB = qsum(sB);
            l_[mt][0] = l_[mt][0] * cA + sA;
            l_[mt][1] = l_[mt][1] * cB + sB;
            m_[mt][0] = nmA; m_[mt][1] = nmB;
            #pragma unroll
            for (int nt = 0; nt < 8; nt++) {
                o[mt][nt][0] *= cA; o[mt][nt][1] *= cA;
                o[mt][nt][2] *= cB; o[mt][nt][3] *= cB;
            }
        }
        __syncwarp();

        // ---- O += P @ V ----
        #pragma unroll
        for (int k8 = 0; k8 < 8; k8++) {
            const int k0 = k8 * 8;
            uint32_t pa[2][4];
            #pragma unroll
            for (int mt = 0; mt < 2; mt++) {
                int r = wid * 32 + mt * 16 + g;
                pa[mt][0] = __float_as_uint(Ps[r * PSTR + k0 + tg]);
                pa[mt][1] = __float_as_uint(Ps[(r + 8) * PSTR + k0 + tg]);
                pa[mt][2] = __float_as_uint(Ps[r * PSTR + k0 + tg + 4]);
                pa[mt][3] = __float_as_uint(Ps[(r + 8) * PSTR + k0 + tg + 4]);
            }
            #pragma unroll
            for (int nt = 0; nt < 8; nt++) {
                uint32_t bfr[2];
                bfr[0] = __float_as_uint(Vs[(k0 + tg) * VSTR + nt * 8 + g]);
                bfr[1] = __float_as_uint(Vs[(k0 + tg + 4) * VSTR + nt * 8 + g]);
                mma8(o[0][nt], pa[0], bfr);
                mma8(o[1][nt], pa[1], bfr);
            }
        }
        __syncthreads();   // all warps done with stage kt before it is reloaded
    }

    // Epilogue: ctx = O / l, tf32-rounded (feeds tf32 out-projection)
    #pragma unroll
    for (int mt = 0; mt < 2; mt++) {
        float invA = 1.f / l_[mt][0];
        float invB = 1.f / l_[mt][1];
        int rg = b * kN + q0 + wid * 32 + mt * 16 + g;
        #pragma unroll
        for (int nt = 0; nt < 8; nt++) {
            int col = h * kHS + nt * 8 + 2 * tg;
            float2 v0 = { tf32_rna(o[mt][nt][0] * invA), tf32_rna(o[mt][nt][1] * invA) };
            float2 v1 = { tf32_rna(o[mt][nt][2] * invB), tf32_rna(o[mt][nt][3] * invB) };
            *(float2*)(ctx + (size_t)rg * kD + col) = v0;
            *(float2*)(ctx + (size_t)(rg + 8) * kD + col) = v1;
        }
    }
}

// ---------------------------------------------------------------------------
extern "C" void kernel_launch(void* const* d_in, const int* in_sizes, int n_in,
                              void* d_out, int out_size)
{
    const float* x         = (const float*)d_in[0];
    const float* attn_mask = (const float*)d_in[1];
    const float* Wqkv      = (const float*)d_in[2];
    const float* Wout      = (const float*)d_in[3];
    const float* bout      = (const float*)d_in[4];
    float* out = (float*)d_out;

    float *qkvbuf, *ctxbuf, *xr, *wqkvT, *woutT;
    cudaGetSymbolAddress((void**)&qkvbuf, g_qkv);
    cudaGetSymbolAddress((void**)&ctxbuf, g_ctx);
    cudaGetSymbolAddress((void**)&xr, g_xr);
    cudaGetSymbolAddress((void**)&wqkvT, g_wqkvT);
    cudaGetSymbolAddress((void**)&woutT, g_woutT);

    cudaFuncSetAttribute(gemm_mma, cudaFuncAttributeMaxDynamicSharedMemorySize,
                         GEMM_SMEM);
    cudaFuncSetAttribute(flash_mma, cudaFuncAttributeMaxDynamicSharedMemorySize,
                         FLASH_SMEM);

    // Pre-pass: round x to tf32; transpose+round weights
    {
        int n4 = kM * kD / 4;
        round_tf32_vec<<<(n4 + 255) / 256, 256>>>((const float4*)x, (float4*)xr, n4);
        transpose_tf32<<<dim3(3 * kD / 32, kD / 32), dim3(32, 8)>>>(Wqkv, wqkvT, kD, 3 * kD);
        transpose_tf32<<<dim3(kD / 32, kD / 32), dim3(32, 8)>>>(Wout, woutT, kD, kD);
    }

    // 1) qkv = x @ Wqkv, output tf32-rounded (feeds flash)
    gemm_mma<<<dim3(3 * kD / 256, kM / 128), 256, GEMM_SMEM>>>(
        xr, wqkvT, nullptr, qkvbuf, kM, 3 * kD, kD, 1);

    // 2) attention
    flash_mma<<<dim3(kN / 128, kB * kH), 128, FLASH_SMEM>>>(
        qkvbuf, attn_mask, ctxbuf);

    // 3) out = ctx @ Wout + bout (full fp32 output)
    gemm_mma<<<dim3(kD / 256, kM / 128), 256, GEMM_SMEM>>>(
        ctxbuf, woutT, bout, out, kM, kD, kD, 0);
}